// round 9
// baseline (speedup 1.0000x reference)
#include <cuda_runtime.h>
#include <math.h>
#include <stdint.h>

#define MM    4095
#define NT    315            // tiles (13*315 = 4095)
#define T     13
#define NTILE 157            // off-diag tiles per anti-diagonal
#define CPT   7
#define THREADS 576
#define SLOTS 82             // slot handles tiles m=slot+1 and (if slot<75) m=slot+83
#define ROWPAD 160           // float2 slots per cell row (157 used, padded for 16B align)
#define NPAIRS (4095LL*2048LL)

// Off-diagonal rotations: [sigma][cell 0..168][m-1 0..156] (rows padded to ROWPAD)
__device__ float2 g_csF[(size_t)NT * 169 * ROWPAD];   // ~68 MB
// Diagonal-tile rotations, dense [A][ia*13+ib] (specials at ia==ib)
__device__ float2 g_csD[NT * 169];

__global__ void precompute(const float* __restrict__ thetas,
                           const int*   __restrict__ round_theta) {
    long long idx = blockIdx.x * (long long)blockDim.x + threadIdx.x;
    if (idx >= NPAIRS) return;
    int r = (int)(idx >> 11), k = (int)(idx & 2047);
    float th = thetas[round_theta[idx]];
    float s, c; sincosf(th, &s, &c);
    if (k == 0) {                       // special: rows (r, 4095), i = r
        int u = (int)((2048LL * r) % MM);
        int A = u / T, ia = u - A * T;
        g_csD[A * 169 + ia * T + ia] = make_float2(c, s);
    } else {
        int a0 = r + k; if (a0 >= MM) a0 -= MM;
        int b0 = r - k; if (b0 < 0)   b0 += MM;
        int i = min(a0, b0), j = max(a0, b0);
        int ui = (int)((2048LL * i) % MM);
        int uj = (int)((2048LL * j) % MM);
        int ua = min(ui, uj), ub = max(ui, uj);
        float sg = (ua == ui) ? s : -s;     // orient for (x=ua-row, y=ub-row)
        int A = ua / T, ia = ua - A * T;
        int B = ub / T, ib = ub - B * T;
        if (A == B) {
            g_csD[A * 169 + ia * T + ib] = make_float2(c, sg);
        } else {
            int d   = ia + ib;
            int sig = A + B; if (sig >= NT) sig -= NT;
            int aD  = (sig * 158) % NT;     // 2*aD == sig (mod 315)
            int mm  = A - aD; if (mm < 0) mm += NT;
            int m   = (mm <= NTILE) ? mm : NT - mm;
            int cell = (d < T) ? d * (d + 1) / 2 + ia
                               : 91 + (d - T) * (38 - d) / 2 + ia - (d - 12);
            g_csF[((size_t)sig * 169 + cell) * ROWPAD + (m - 1)] = make_float2(c, sg);
        }
    }
}

__device__ __forceinline__ void rot(float& x, float& y, float2 cs) {
    float xo = x, yo = y;
    x = fmaf(cs.x, xo, -(cs.y * yo));
    y = fmaf(cs.y, xo,  (cs.x * yo));
}

__device__ __forceinline__ void tileAB(int sigma, int m, int& A, int& B) {
    int aD = (sigma * 158) % NT;
    int a = aD + m; if (a >= NT) a -= NT;
    int b = aD - m; if (b < 0)   b += NT;
    A = min(a, b); B = max(a, b);
}

// Diagonal phase for step s (7 threads): early half of diag tile aE (2aE==s),
// late half of diag tile aL (2aL==s-1), specials chained through row 4095.
__device__ __forceinline__ void visit_diag(float* __restrict__ sm,
                                           int aE, int aL, int cc) {
    const float2* __restrict__ csE = g_csD + aE * 169;
    const float2* __restrict__ csL = g_csD + aL * 169;
    float re[T], rl[T];
    float* pe = sm + 91 * aE + cc;
    float* pl = sm + 91 * aL + cc;
    float sp = sm[MM * CPT + cc];
    #pragma unroll
    for (int q = 0; q < T; ++q) { re[q] = pe[q * CPT]; rl[q] = pl[q * CPT]; }
    #pragma unroll
    for (int dp = 0; dp < T; ++dp) {             // round 13s + dp
        #pragma unroll
        for (int p = 0; 2 * p < dp; ++p) rot(re[p], re[dp - p], csE[p * T + (dp - p)]);
        if ((dp & 1) == 0) rot(re[dp >> 1], sp, csE[(dp >> 1) * T + (dp >> 1)]);
        if (dp <= T - 2) {
            const int dd = dp + T;
            #pragma unroll
            for (int p = dp + 1; 2 * p < dd; ++p) rot(rl[p], rl[dd - p], csL[p * T + (dd - p)]);
            if ((dd & 1) == 0) rot(rl[dd >> 1], sp, csL[(dd >> 1) * T + (dd >> 1)]);
        }
    }
    #pragma unroll
    for (int q = 0; q < T; ++q) { pe[q * CPT] = re[q]; pl[q * CPT] = rl[q]; }
    sm[MM * CPT + cc] = sp;
}

__device__ __forceinline__ void load13(float (&r)[T], const float* p) {
    #pragma unroll
    for (int q = 0; q < T; ++q) r[q] = p[q * CPT];
}
__device__ __forceinline__ void store13(const float (&r)[T], float* p) {
    #pragma unroll
    for (int q = 0; q < T; ++q) p[q * CPT] = r[q];
}

__device__ __forceinline__ void cpasync16(float* sdst, const char* gsrc) {
    uint32_t sa = (uint32_t)__cvta_generic_to_shared(sdst);
    asm volatile("cp.async.cg.shared.global [%0], [%1], 16;\n" :: "r"(sa), "l"(gsrc));
}
__device__ __forceinline__ void cp_commit() {
    asm volatile("cp.async.commit_group;\n");
}
__device__ __forceinline__ void cp_wait0() {
    asm volatile("cp.async.wait_group 0;\n" ::: "memory");
}

// Stage cells [C0, C1) of sigma's table into smem buffer (cooperative).
__device__ __forceinline__ void stage(int sigma, int C0, int C1, float* buf, int tid) {
    const char* gsrc = (const char*)(g_csF + ((size_t)sigma * 169 + C0) * ROWPAD);
    const int n16 = (C1 - C0) * (ROWPAD * 8 / 16);   // 80 16B-units per cell
    for (int u = tid; u < n16; u += THREADS)
        cpasync16(buf + u * 4, gsrc + u * 16);
}

// Apply cells [C0, C1) (staged at base CS) to this slot's tile(s).
template<int CS, int C0, int C1>
__device__ __forceinline__ void chunk_visit(const float2* __restrict__ buf,
                                            int m1, int m2, bool has2,
                                            float (&ra1)[T], float (&rb1)[T],
                                            float (&ra2)[T], float (&rb2)[T]) {
    #pragma unroll
    for (int d = 0; d < 2 * T - 1; ++d) {
        const int plo = (d < T) ? 0 : d - (T - 1);
        const int phi = (d < T) ? d : (T - 1);
        #pragma unroll
        for (int p = plo; p <= phi; ++p) {
            const int cell = (d < T) ? d * (d + 1) / 2 + p
                                     : 91 + (d - T) * (38 - d) / 2 + p - (d - 12);
            if (cell >= C0 && cell < C1) {
                const float2* row = buf + (cell - CS) * ROWPAD;
                rot(ra1[p], rb1[d - p], row[m1 - 1]);
                if (has2) rot(ra2[p], rb2[d - p], row[m2 - 1]);
            }
        }
    }
}

#define SLAB_F  (4096 * CPT)          // 28672 floats
#define BUF_F   (43 * ROWPAD * 2)     // 13760 floats (capacity 43 cells)
#define SMEM_F  (SLAB_F + 2 * BUF_F)  // 56192 floats = 224768 B

__global__ void __launch_bounds__(THREADS, 1)
rotmat_kernel(float* __restrict__ out) {
    extern __shared__ float sm[];                 // slab | buf0 | buf1
    float* buf0 = sm + SLAB_F;
    float* buf1 = buf0 + BUF_F;
    const int c0   = blockIdx.x * CPT;
    const int cols = min(4096 - c0, CPT);
    const int tid  = threadIdx.x;
    const int slot = tid / CPT;
    const int cc   = tid - slot * CPT;
    const bool has1 = (slot < SLOTS);
    const bool has2 = (slot < NTILE - SLOTS);     // slot < 75
    const int m1 = slot + 1;
    const int m2 = has2 ? slot + 1 + SLOTS : 1;

    for (int i = tid; i < SLAB_F; i += THREADS) sm[i] = 0.0f;
    __syncthreads();
    if (tid < cols) {                             // identity in u-coordinates
        int c = c0 + tid;
        int u = (c == MM) ? MM : (int)((2048LL * c) % MM);
        sm[u * CPT + tid] = 1.0f;
    }
    __syncthreads();

    float ra1[T], rb1[T], ra2[T], rb2[T];

    // ---- Prologue: late halves (cells 91..168) of sigma = 314 ----
    stage(NT - 1, 91, 127, buf0, tid); cp_commit();
    cp_wait0(); __syncthreads();
    stage(NT - 1, 127, 169, buf1, tid); cp_commit();
    {
        int A1, B1, A2, B2;
        tileAB(NT - 1, m1, A1, B1); tileAB(NT - 1, m2, A2, B2);
        float* pa1 = sm + 91 * A1 + cc; float* pb1 = sm + 91 * B1 + cc;
        float* pa2 = sm + 91 * A2 + cc; float* pb2 = sm + 91 * B2 + cc;
        if (has1) { load13(ra1, pa1); load13(rb1, pb1);
                    if (has2) { load13(ra2, pa2); load13(rb2, pb2); } }
        if (has1) chunk_visit<91, 91, 127>((const float2*)buf0, m1, m2, has2, ra1, rb1, ra2, rb2);
        cp_wait0(); __syncthreads();
        stage(0, 0, 43, buf0, tid); cp_commit();
        if (has1) {
            chunk_visit<127, 127, 169>((const float2*)buf1, m1, m2, has2, ra1, rb1, ra2, rb2);
            store13(ra1, pa1); store13(rb1, pb1);
            if (has2) { store13(ra2, pa2); store13(rb2, pb2); }
        }
    }
    __syncthreads();
    // invariant at loop top: chunk (s, [0,43)) in flight into buf0; rows in smem

    for (int s = 0; s < NT - 1; ++s) {
        if (tid < CPT) {
            int aE = (s * 158) % NT;
            int aL = aE - 158; if (aL < 0) aL += NT;
            visit_diag(sm, aE, aL, tid);
        }
        cp_wait0(); __syncthreads();              // chunk0 ready + diag visible
        stage(s, 43, 85, buf1, tid); cp_commit();

        int A1, B1, A2, B2;
        tileAB(s, m1, A1, B1); tileAB(s, m2, A2, B2);
        float* pa1 = sm + 91 * A1 + cc; float* pb1 = sm + 91 * B1 + cc;
        float* pa2 = sm + 91 * A2 + cc; float* pb2 = sm + 91 * B2 + cc;
        if (has1) { load13(ra1, pa1); load13(rb1, pb1);
                    if (has2) { load13(ra2, pa2); load13(rb2, pb2); }
                    chunk_visit<0, 0, 43>((const float2*)buf0, m1, m2, has2, ra1, rb1, ra2, rb2); }
        cp_wait0(); __syncthreads();
        stage(s, 85, 127, buf0, tid); cp_commit();
        if (has1) chunk_visit<43, 43, 85>((const float2*)buf1, m1, m2, has2, ra1, rb1, ra2, rb2);
        cp_wait0(); __syncthreads();
        stage(s, 127, 169, buf1, tid); cp_commit();
        if (has1) chunk_visit<85, 85, 127>((const float2*)buf0, m1, m2, has2, ra1, rb1, ra2, rb2);
        cp_wait0(); __syncthreads();
        stage(s + 1, 0, 43, buf0, tid); cp_commit();   // s=313 -> (314,[0,43)) too
        if (has1) {
            chunk_visit<127, 127, 169>((const float2*)buf1, m1, m2, has2, ra1, rb1, ra2, rb2);
            store13(ra1, pa1); store13(rb1, pb1);
            if (has2) { store13(ra2, pa2); store13(rb2, pb2); }
        }
        __syncthreads();
    }

    // ---- Epilogue: s = 314, early halves only (cells 0..90) ----
    {
        const int s = NT - 1;
        if (tid < CPT) {
            int aE = (s * 158) % NT;
            int aL = aE - 158; if (aL < 0) aL += NT;
            visit_diag(sm, aE, aL, tid);
        }
        cp_wait0(); __syncthreads();
        stage(s, 43, 85, buf1, tid); cp_commit();

        int A1, B1, A2, B2;
        tileAB(s, m1, A1, B1); tileAB(s, m2, A2, B2);
        float* pa1 = sm + 91 * A1 + cc; float* pb1 = sm + 91 * B1 + cc;
        float* pa2 = sm + 91 * A2 + cc; float* pb2 = sm + 91 * B2 + cc;
        if (has1) { load13(ra1, pa1); load13(rb1, pb1);
                    if (has2) { load13(ra2, pa2); load13(rb2, pb2); }
                    chunk_visit<0, 0, 43>((const float2*)buf0, m1, m2, has2, ra1, rb1, ra2, rb2); }
        cp_wait0(); __syncthreads();
        stage(s, 85, 91, buf0, tid); cp_commit();
        if (has1) chunk_visit<43, 43, 85>((const float2*)buf1, m1, m2, has2, ra1, rb1, ra2, rb2);
        cp_wait0(); __syncthreads();
        if (has1) {
            chunk_visit<85, 85, 91>((const float2*)buf0, m1, m2, has2, ra1, rb1, ra2, rb2);
            store13(ra1, pa1); store13(rb1, pb1);
            if (has2) { store13(ra2, pa2); store13(rb2, pb2); }
        }
        __syncthreads();
    }

    // Writeback: slab u-row v -> absolute row x = 2v mod 4095 (4095 -> 4095)
    for (int v = tid; v < 4096; v += THREADS) {
        int x = (v == MM) ? MM : ((2 * v) % MM);
        const float* src = sm + v * CPT;
        float* dst = out + (size_t)x * 4096 + c0;
        #pragma unroll
        for (int k = 0; k < CPT; ++k) if (k < cols) dst[k] = src[k];
    }
}

extern "C" void kernel_launch(void* const* d_in, const int* in_sizes, int n_in,
                              void* d_out, int out_size) {
    const float* thetas      = (const float*)d_in[0];
    const int*   round_theta = (const int*)d_in[3];
    float*       out         = (float*)d_out;
    (void)in_sizes; (void)n_in; (void)out_size;

    const int smem = SMEM_F * (int)sizeof(float);       // 224,768 B
    cudaFuncSetAttribute(rotmat_kernel,
                         cudaFuncAttributeMaxDynamicSharedMemorySize, smem);

    precompute<<<(int)((NPAIRS + 255) / 256), 256>>>(thetas, round_theta);

    const int nblocks = (4096 + CPT - 1) / CPT;         // 586
    rotmat_kernel<<<nblocks, THREADS, smem>>>(out);
}

// round 10
// speedup vs baseline: 1.6925x; 1.6925x over previous
#include <cuda_runtime.h>
#include <math.h>
#include <stdint.h>

#define MM    4095
#define T     15
#define NT    273            // 15 * 273 = 4095
#define NTILE 136            // off-diag tiles per sigma
#define INV2  137            // 2*137 = 274 == 1 (mod 273)
#define CELLS 225            // T*T
#define CPT   4
#define THREADS 544          // 136 slots * 4 cols
#define DPAD  232            // padded diag-tile length (float2), 232*8=1856 (16B mult)
#define CHUNK 20
#define NPAIRS (4095LL*2048LL)

// Off-diag rotations: [sigma][cell][m-1], cell rows of 136 float2 (1088 B)
__device__ float2 g_csF[(size_t)NT * CELLS * NTILE];   // ~66.9 MB
// Diagonal-tile rotations: [A][ia*15+ib] (specials at ia==ib), padded rows
__device__ float2 g_csD[NT * DPAD];

__host__ __device__ __forceinline__ constexpr int cell_of(int d, int p) {
    return (d < T) ? d * (d + 1) / 2 + p
                   : 120 + (d - T) * (3 * T - 1 - d) / 2 + (p - (d - (T - 1)));
}

__global__ void precompute(const float* __restrict__ thetas,
                           const int*   __restrict__ round_theta) {
    long long idx = blockIdx.x * (long long)blockDim.x + threadIdx.x;
    if (idx >= NPAIRS) return;
    int r = (int)(idx >> 11), k = (int)(idx & 2047);
    float th = thetas[round_theta[idx]];
    float s, c; sincosf(th, &s, &c);
    if (k == 0) {                         // special: rows (r, 4095), i = r
        int u = (int)((2048LL * r) % MM);
        int A = u / T, ia = u % T;
        g_csD[A * DPAD + ia * T + ia] = make_float2(c, s);
    } else {
        int a0 = r + k; if (a0 >= MM) a0 -= MM;
        int b0 = r - k; if (b0 < 0)   b0 += MM;
        int i = min(a0, b0), j = max(a0, b0);
        int ui = (int)((2048LL * i) % MM);
        int uj = (int)((2048LL * j) % MM);
        int ua = min(ui, uj), ub = max(ui, uj);
        float sg = (ua == ui) ? s : -s;   // orient for (x = ua-row, y = ub-row)
        int A = ua / T, ia = ua % T;
        int B = ub / T, ib = ub % T;
        if (A == B) {
            g_csD[A * DPAD + ia * T + ib] = make_float2(c, sg);
        } else {
            int d   = ia + ib;
            int sig = A + B; if (sig >= NT) sig -= NT;
            int aD  = (sig * INV2) % NT;
            int mm  = A - aD; if (mm < 0) mm += NT;
            int m   = (mm <= NTILE) ? mm : NT - mm;
            g_csF[((size_t)sig * CELLS + cell_of(d, ia)) * NTILE + (m - 1)]
                = make_float2(c, sg);
        }
    }
}

__device__ __forceinline__ void rot(float& x, float& y, float2 cs) {
    float xo = x, yo = y;
    x = fmaf(cs.x, xo, -(cs.y * yo));
    y = fmaf(cs.y, xo,  (cs.x * yo));
}

__device__ __forceinline__ void tileAB(int sigma, int m, int& A, int& B) {
    int aD = (sigma * INV2) % NT;
    int a = aD + m; if (a >= NT) a -= NT;
    int b = aD - m; if (b < 0)   b += NT;
    A = min(a, b); B = max(a, b);
}

__device__ __forceinline__ void cpasync16(float* sdst, const char* gsrc) {
    uint32_t sa = (uint32_t)__cvta_generic_to_shared(sdst);
    asm volatile("cp.async.cg.shared.global [%0], [%1], 16;\n" :: "r"(sa), "l"(gsrc));
}
__device__ __forceinline__ void cp_commit() { asm volatile("cp.async.commit_group;\n"); }
__device__ __forceinline__ void cp_wait0()  { asm volatile("cp.async.wait_group 0;\n" ::: "memory"); }

// Stage cells [C0,C1) of sigma into smem buffer. 68 16B-units per cell.
__device__ __forceinline__ void stage(int sig, int C0, int C1, float* buf, int tid) {
    const char* g = (const char*)(g_csF + ((size_t)sig * CELLS + C0) * NTILE);
    const int n16 = (C1 - C0) * (NTILE * 8 / 16);
    for (int u = tid; u < n16; u += THREADS)
        cpasync16(buf + u * 4, g + (size_t)u * 16);
}
// Stage the two diag tiles (aE: 2aE==s, aL: 2aL==s-1) for step s.
__device__ __forceinline__ void stage_diag(int s, float* bufD, int tid) {
    int aE = (s * INV2) % NT;
    int aL = aE - INV2; if (aL < 0) aL += NT;
    const char* gE = (const char*)(g_csD + aE * DPAD);
    const char* gL = (const char*)(g_csD + aL * DPAD);
    for (int u = tid; u < 113; u += THREADS) {      // 113*16 = 1808 >= 1800
        cpasync16(bufD + u * 4, gE + u * 16);
        cpasync16(bufD + DPAD * 2 + u * 4, gL + u * 16);
    }
}

// Apply cells [C0,C1) (at buffer base) to this slot's tile. bufm = buf + (m-1).
template<int C0, int C1>
__device__ __forceinline__ void chunk_visit(const float2* __restrict__ bufm,
                                            float (&ra)[T], float (&rb)[T]) {
    #pragma unroll
    for (int d = 0; d < 2 * T - 1; ++d) {
        const int plo = (d < T) ? 0 : d - (T - 1);
        const int phi = (d < T) ? d : (T - 1);
        #pragma unroll
        for (int p = plo; p <= phi; ++p) {
            const int cell = cell_of(d, p);
            if (cell >= C0 && cell < C1)
                rot(ra[p], rb[d - p], bufm[(cell - C0) * NTILE]);
        }
    }
}

// Diagonal phase for step s (4 threads): early half of tile aE (2aE==s), late
// half of tile aL (2aL==s-1), specials chained through row 4095, round order.
__device__ __forceinline__ void visit_diag(float* __restrict__ sm_,
                                           const float2* __restrict__ dbuf,
                                           int s, int cc) {
    int aE = (s * INV2) % NT;
    int aL = aE - INV2; if (aL < 0) aL += NT;
    const float2* csE = dbuf;
    const float2* csL = dbuf + DPAD;
    float re[T], rl[T];
    float* pe = sm_ + 60 * aE + cc;      // 60 = 15 rows * stride 4
    float* pl = sm_ + 60 * aL + cc;
    float sp = sm_[MM * CPT + cc];
    #pragma unroll
    for (int q = 0; q < T; ++q) { re[q] = pe[q * CPT]; rl[q] = pl[q * CPT]; }
    #pragma unroll
    for (int dp = 0; dp < T; ++dp) {                 // round 15s + dp
        #pragma unroll
        for (int p = 0; 2 * p < dp; ++p) rot(re[p], re[dp - p], csE[p * T + (dp - p)]);
        if ((dp & 1) == 0) rot(re[dp >> 1], sp, csE[(dp >> 1) * (T + 1)]);
        if (dp <= T - 2) {
            const int dd = dp + T;
            #pragma unroll
            for (int p = dp + 1; 2 * p < dd; ++p) rot(rl[p], rl[dd - p], csL[p * T + (dd - p)]);
            if ((dd & 1) == 0) rot(rl[dd >> 1], sp, csL[(dd >> 1) * (T + 1)]);
        }
    }
    #pragma unroll
    for (int q = 0; q < T; ++q) { pe[q * CPT] = re[q]; pl[q * CPT] = rl[q]; }
    sm_[MM * CPT + cc] = sp;
}

__device__ __forceinline__ void load15(float (&r)[T], const float* p) {
    #pragma unroll
    for (int q = 0; q < T; ++q) r[q] = p[q * CPT];
}
__device__ __forceinline__ void store15(const float (&r)[T], float* p) {
    #pragma unroll
    for (int q = 0; q < T; ++q) p[q * CPT] = r[q];
}

#define SLAB_F 16384                       // 4096 rows * stride 4
#define DBUF_F (2 * DPAD * 2)              // 928 floats
#define CBUF_F (CHUNK * NTILE * 2)         // 5440 floats per buffer
#define SMEM_F (SLAB_F + DBUF_F + 2 * CBUF_F)   // 28192 floats = 112768 B

// Pipeline macro: wait current chunk, barrier, issue next stage, compute.
// Buffer parity is fixed by global chunk index (C0/CHUNK).
#define PIPE(C0, C1, STAGE_STMT) do {                                          \
    cp_wait0(); __syncthreads();                                               \
    { STAGE_STMT; } cp_commit();                                               \
    const float2* bm_ = (const float2*)((((C0) / CHUNK) & 1) ? buf1 : buf0)    \
                        + (m - 1);                                             \
    chunk_visit<C0, C1>(bm_, ra, rb);                                          \
} while (0)

__global__ void __launch_bounds__(THREADS, 2)
rotmat_kernel(float* __restrict__ out) {
    extern __shared__ float sm[];          // slab | bufD | buf0 | buf1
    float* bufD = sm + SLAB_F;
    float* buf0 = bufD + DBUF_F;
    float* buf1 = buf0 + CBUF_F;
    const int c0  = blockIdx.x * CPT;
    const int tid = threadIdx.x;
    const int slot = tid >> 2;             // 0..135
    const int cc   = tid & 3;
    const int m    = slot + 1;             // tile index 1..136 (exactly one per slot)

    for (int i = tid; i < SLAB_F; i += THREADS) sm[i] = 0.0f;
    __syncthreads();
    if (tid < CPT) {                       // identity in u-coordinates
        int c = c0 + tid;
        int u = (c == MM) ? MM : (int)((2048LL * c) % MM);
        sm[u * CPT + tid] = 1.0f;
    }
    __syncthreads();

    float ra[T], rb[T];
    int A, B;

    // ---- Prologue: late half (cells 120..224) of sigma = 272 ----
    stage(NT - 1, 120, 140, buf0, tid); stage_diag(0, bufD, tid); cp_commit();
    tileAB(NT - 1, m, A, B);
    float* pa = sm + 60 * A + cc;
    float* pb = sm + 60 * B + cc;
    PIPE(120, 140, { stage(NT - 1, 140, 160, buf1, tid);
                     load15(ra, pa); load15(rb, pb); });
    PIPE(140, 160, stage(NT - 1, 160, 180, buf0, tid));
    PIPE(160, 180, stage(NT - 1, 180, 200, buf1, tid));
    PIPE(180, 200, stage(NT - 1, 200, 220, buf0, tid));
    PIPE(200, 220, stage(NT - 1, 220, 225, buf1, tid));
    PIPE(220, 225, stage(0, 0, 20, buf0, tid));
    store15(ra, pa); store15(rb, pb);
    __syncthreads();
    // invariant at loop top: chunk (s,[0,20)) in flight -> buf0; diag(s) in bufD

    for (int s = 0; s < NT - 1; ++s) {
        if (tid < CPT) visit_diag(sm, (const float2*)bufD, s, tid);
        tileAB(s, m, A, B);
        pa = sm + 60 * A + cc;
        pb = sm + 60 * B + cc;
        PIPE(0, 20,   { stage(s, 20, 40, buf1, tid); stage_diag(s + 1, bufD, tid);
                        load15(ra, pa); load15(rb, pb); });
        PIPE(20, 40,   stage(s, 40, 60,  buf0, tid));
        PIPE(40, 60,   stage(s, 60, 80,  buf1, tid));
        PIPE(60, 80,   stage(s, 80, 100, buf0, tid));
        PIPE(80, 100,  stage(s, 100, 120, buf1, tid));
        PIPE(100, 120, stage(s, 120, 140, buf0, tid));
        PIPE(120, 140, stage(s, 140, 160, buf1, tid));
        PIPE(140, 160, stage(s, 160, 180, buf0, tid));
        PIPE(160, 180, stage(s, 180, 200, buf1, tid));
        PIPE(180, 200, stage(s, 200, 220, buf0, tid));
        PIPE(200, 220, stage(s, 220, 225, buf1, tid));
        PIPE(220, 225, stage(s + 1, 0, 20, buf0, tid));
        store15(ra, pa); store15(rb, pb);
        __syncthreads();
    }

    // ---- Epilogue: s = 272, early half (cells 0..119) ----
    {
        const int s = NT - 1;
        if (tid < CPT) visit_diag(sm, (const float2*)bufD, s, tid);
        tileAB(s, m, A, B);
        pa = sm + 60 * A + cc;
        pb = sm + 60 * B + cc;
        PIPE(0, 20,   { stage(s, 20, 40, buf1, tid);
                        load15(ra, pa); load15(rb, pb); });
        PIPE(20, 40,   stage(s, 40, 60,  buf0, tid));
        PIPE(40, 60,   stage(s, 60, 80,  buf1, tid));
        PIPE(60, 80,   stage(s, 80, 100, buf0, tid));
        PIPE(80, 100,  stage(s, 100, 120, buf1, tid));
        PIPE(100, 120, { });
        store15(ra, pa); store15(rb, pb);
        __syncthreads();
    }

    // Writeback: slab u-row v -> absolute row x = 2v mod 4095 (4095 -> 4095)
    for (int v = tid; v < 4096; v += THREADS) {
        int x = (v == MM) ? MM : ((2 * v) % MM);
        float4 val = *(const float4*)(sm + v * CPT);
        *(float4*)(out + (size_t)x * 4096 + c0) = val;
    }
}

extern "C" void kernel_launch(void* const* d_in, const int* in_sizes, int n_in,
                              void* d_out, int out_size) {
    const float* thetas      = (const float*)d_in[0];
    const int*   round_theta = (const int*)d_in[3];
    float*       out         = (float*)d_out;
    (void)in_sizes; (void)n_in; (void)out_size;

    const int smem = SMEM_F * (int)sizeof(float);       // 112,768 B
    cudaFuncSetAttribute(rotmat_kernel,
                         cudaFuncAttributeMaxDynamicSharedMemorySize, smem);

    precompute<<<(int)((NPAIRS + 255) / 256), 256>>>(thetas, round_theta);

    rotmat_kernel<<<4096 / CPT, THREADS, smem>>>(out);
}

// round 11
// speedup vs baseline: 1.8012x; 1.0643x over previous
#include <cuda_runtime.h>
#include <math.h>
#include <stdint.h>

#define MM    4095
#define T     15
#define NT    273            // 15 * 273 = 4095
#define NTILE 136            // off-diag tiles per sigma
#define INV2  137            // 2*137 == 1 (mod 273)
#define CELLS 225            // T*T
#define CPT   4              // columns per CTA (2 per thread, f32x2-packed)
#define THREADS 272          // 136 slots * 2 threads
#define DPAD  232            // padded diag-tile length (float2)
#define CHUNK 20
#define NPAIRS (4095LL*2048LL)

typedef unsigned long long u64_t;

// Off-diag rotations: [sigma][cell][m-1], cell rows of 136 float2 (1088 B)
__device__ float2 g_csF[(size_t)NT * CELLS * NTILE];   // ~66.9 MB
// Diagonal-tile rotations: [A][ia*15+ib] (specials at ia==ib), padded rows
__device__ float2 g_csD[NT * DPAD];

__host__ __device__ __forceinline__ constexpr int cell_of(int d, int p) {
    return (d < T) ? d * (d + 1) / 2 + p
                   : 120 + (d - T) * (3 * T - 1 - d) / 2 + (p - (d - (T - 1)));
}

__global__ void precompute(const float* __restrict__ thetas,
                           const int*   __restrict__ round_theta) {
    long long idx = blockIdx.x * (long long)blockDim.x + threadIdx.x;
    if (idx >= NPAIRS) return;
    int r = (int)(idx >> 11), k = (int)(idx & 2047);
    float th = thetas[round_theta[idx]];
    float s, c; sincosf(th, &s, &c);
    if (k == 0) {                         // special: rows (r, 4095), i = r
        int u = (int)((2048LL * r) % MM);
        int A = u / T, ia = u % T;
        g_csD[A * DPAD + ia * T + ia] = make_float2(c, s);
    } else {
        int a0 = r + k; if (a0 >= MM) a0 -= MM;
        int b0 = r - k; if (b0 < 0)   b0 += MM;
        int i = min(a0, b0), j = max(a0, b0);
        int ui = (int)((2048LL * i) % MM);
        int uj = (int)((2048LL * j) % MM);
        int ua = min(ui, uj), ub = max(ui, uj);
        float sg = (ua == ui) ? s : -s;   // orient for (x = ua-row, y = ub-row)
        int A = ua / T, ia = ua % T;
        int B = ub / T, ib = ub % T;
        if (A == B) {
            g_csD[A * DPAD + ia * T + ib] = make_float2(c, sg);
        } else {
            int d   = ia + ib;
            int sig = A + B; if (sig >= NT) sig -= NT;
            int aD  = (sig * INV2) % NT;
            int mm  = A - aD; if (mm < 0) mm += NT;
            int m   = (mm <= NTILE) ? mm : NT - mm;
            g_csF[((size_t)sig * CELLS + cell_of(d, ia)) * NTILE + (m - 1)]
                = make_float2(c, sg);
        }
    }
}

// Packed Givens rotation on 2 columns: per lane, bit-identical to
// x' = fmaf(c, x, -(s*y)); y' = fmaf(s, x, c*y).
__device__ __forceinline__ void rot2(u64_t& x, u64_t& y, float2 cs) {
    unsigned ci = __float_as_uint(cs.x);
    unsigned si = __float_as_uint(cs.y);
    u64_t c2, s2, t, xo = x;
    asm("mov.b64 %0, {%1, %1};" : "=l"(c2) : "r"(ci));
    asm("mov.b64 %0, {%1, %1};" : "=l"(s2) : "r"(si));
    asm("mul.rn.f32x2 %0, %1, %2;" : "=l"(t) : "l"(s2), "l"(y));
    t ^= 0x8000000080000000ULL;                      // exact negation
    asm("fma.rn.f32x2 %0, %1, %2, %3;" : "=l"(x) : "l"(c2), "l"(xo), "l"(t));
    asm("mul.rn.f32x2 %0, %1, %2;" : "=l"(t) : "l"(c2), "l"(y));
    asm("fma.rn.f32x2 %0, %1, %2, %3;" : "=l"(y) : "l"(s2), "l"(xo), "l"(t));
}

__device__ __forceinline__ void tileAB(int sigma, int m, int& A, int& B) {
    int aD = (sigma * INV2) % NT;
    int a = aD + m; if (a >= NT) a -= NT;
    int b = aD - m; if (b < 0)   b += NT;
    A = min(a, b); B = max(a, b);
}

__device__ __forceinline__ void cpasync16(float* sdst, const char* gsrc) {
    uint32_t sa = (uint32_t)__cvta_generic_to_shared(sdst);
    asm volatile("cp.async.cg.shared.global [%0], [%1], 16;\n" :: "r"(sa), "l"(gsrc));
}
__device__ __forceinline__ void cp_commit() { asm volatile("cp.async.commit_group;\n"); }
__device__ __forceinline__ void cp_wait0()  { asm volatile("cp.async.wait_group 0;\n" ::: "memory"); }

// Stage cells [C0,C1) of sigma into smem buffer. 68 16B-units per cell.
__device__ __forceinline__ void stage(int sig, int C0, int C1, float* buf, int tid) {
    const char* g = (const char*)(g_csF + ((size_t)sig * CELLS + C0) * NTILE);
    const int n16 = (C1 - C0) * (NTILE * 8 / 16);
    for (int u = tid; u < n16; u += THREADS)
        cpasync16(buf + u * 4, g + (size_t)u * 16);
}
// Stage the two diag tiles (aE: 2aE==s, aL: 2aL==s-1) for step s.
__device__ __forceinline__ void stage_diag(int s, float* bufD, int tid) {
    int aE = (s * INV2) % NT;
    int aL = aE - INV2; if (aL < 0) aL += NT;
    const char* gE = (const char*)(g_csD + aE * DPAD);
    const char* gL = (const char*)(g_csD + aL * DPAD);
    if (tid < 113) {                     // 113*16 = 1808 >= 1800
        cpasync16(bufD + tid * 4, gE + tid * 16);
        cpasync16(bufD + DPAD * 2 + tid * 4, gL + tid * 16);
    }
}

// Apply cells [C0,C1) (at buffer base) to this slot's tile. bufm = buf + (m-1).
template<int C0, int C1>
__device__ __forceinline__ void chunk_visit(const float2* __restrict__ bufm,
                                            u64_t (&ra)[T], u64_t (&rb)[T]) {
    #pragma unroll
    for (int d = 0; d < 2 * T - 1; ++d) {
        const int plo = (d < T) ? 0 : d - (T - 1);
        const int phi = (d < T) ? d : (T - 1);
        #pragma unroll
        for (int p = plo; p <= phi; ++p) {
            const int cell = cell_of(d, p);
            if (cell >= C0 && cell < C1)
                rot2(ra[p], rb[d - p], bufm[(cell - C0) * NTILE]);
        }
    }
}

// Diagonal phase for step s (2 threads, 2 packed cols each): early half of
// tile aE (2aE==s), late half of tile aL (2aL==s-1), specials chained through
// row 4095 in exact round order.
__device__ __forceinline__ void visit_diag(float* __restrict__ sm_,
                                           const float2* __restrict__ dbuf,
                                           int s, int cc) {
    int aE = (s * INV2) % NT;
    int aL = aE - INV2; if (aL < 0) aL += NT;
    const float2* csE = dbuf;
    const float2* csL = dbuf + DPAD;
    u64_t re[T], rl[T];
    float* pe = sm_ + 60 * aE + 2 * cc;      // 60 = 15 rows * stride 4
    float* pl = sm_ + 60 * aL + 2 * cc;
    u64_t sp = *(u64_t*)(sm_ + MM * CPT + 2 * cc);
    #pragma unroll
    for (int q = 0; q < T; ++q) { re[q] = *(u64_t*)(pe + q * CPT);
                                  rl[q] = *(u64_t*)(pl + q * CPT); }
    #pragma unroll
    for (int dp = 0; dp < T; ++dp) {                 // round 15s + dp
        #pragma unroll
        for (int p = 0; 2 * p < dp; ++p) rot2(re[p], re[dp - p], csE[p * T + (dp - p)]);
        if ((dp & 1) == 0) rot2(re[dp >> 1], sp, csE[(dp >> 1) * (T + 1)]);
        if (dp <= T - 2) {
            const int dd = dp + T;
            #pragma unroll
            for (int p = dp + 1; 2 * p < dd; ++p) rot2(rl[p], rl[dd - p], csL[p * T + (dd - p)]);
            if ((dd & 1) == 0) rot2(rl[dd >> 1], sp, csL[(dd >> 1) * (T + 1)]);
        }
    }
    #pragma unroll
    for (int q = 0; q < T; ++q) { *(u64_t*)(pe + q * CPT) = re[q];
                                  *(u64_t*)(pl + q * CPT) = rl[q]; }
    *(u64_t*)(sm_ + MM * CPT + 2 * cc) = sp;
}

__device__ __forceinline__ void load15(u64_t (&r)[T], const float* p) {
    #pragma unroll
    for (int q = 0; q < T; ++q) r[q] = *(const u64_t*)(p + q * CPT);
}
__device__ __forceinline__ void store15(const u64_t (&r)[T], float* p) {
    #pragma unroll
    for (int q = 0; q < T; ++q) *(u64_t*)(p + q * CPT) = r[q];
}

#define SLAB_F 16384                       // 4096 rows * stride 4
#define DBUF_F (2 * DPAD * 2)              // 928 floats
#define CBUF_F (CHUNK * NTILE * 2)         // 5440 floats per buffer
#define SMEM_F (SLAB_F + DBUF_F + 2 * CBUF_F)   // 28192 floats = 112768 B

// Pipeline: wait current chunk, barrier, issue next stage, compute.
#define PIPE(C0, C1, STAGE_STMT) do {                                          \
    cp_wait0(); __syncthreads();                                               \
    { STAGE_STMT; } cp_commit();                                               \
    const float2* bm_ = (const float2*)((((C0) / CHUNK) & 1) ? buf1 : buf0)    \
                        + (m - 1);                                             \
    chunk_visit<C0, C1>(bm_, ra, rb);                                          \
} while (0)

__global__ void __launch_bounds__(THREADS, 2)
rotmat_kernel(float* __restrict__ out) {
    extern __shared__ float sm[];          // slab | bufD | buf0 | buf1
    float* bufD = sm + SLAB_F;
    float* buf0 = bufD + DBUF_F;
    float* buf1 = buf0 + CBUF_F;
    const int c0  = blockIdx.x * CPT;
    const int tid = threadIdx.x;
    const int slot = tid >> 1;             // 0..135
    const int cc   = tid & 1;              // packed column pair within slot
    const int m    = slot + 1;             // tile index 1..136

    for (int i = tid; i < SLAB_F; i += THREADS) sm[i] = 0.0f;
    __syncthreads();
    if (tid < CPT) {                       // identity in u-coordinates
        int c = c0 + tid;
        int u = (c == MM) ? MM : (int)((2048LL * c) % MM);
        sm[u * CPT + tid] = 1.0f;
    }
    __syncthreads();

    u64_t ra[T], rb[T];
    int A, B;

    // ---- Prologue: late half (cells 120..224) of sigma = 272 ----
    stage(NT - 1, 120, 140, buf0, tid); stage_diag(0, bufD, tid); cp_commit();
    tileAB(NT - 1, m, A, B);
    float* pa = sm + 60 * A + 2 * cc;
    float* pb = sm + 60 * B + 2 * cc;
    PIPE(120, 140, { stage(NT - 1, 140, 160, buf1, tid);
                     load15(ra, pa); load15(rb, pb); });
    PIPE(140, 160, stage(NT - 1, 160, 180, buf0, tid));
    PIPE(160, 180, stage(NT - 1, 180, 200, buf1, tid));
    PIPE(180, 200, stage(NT - 1, 200, 220, buf0, tid));
    PIPE(200, 220, stage(NT - 1, 220, 225, buf1, tid));
    PIPE(220, 225, stage(0, 0, 20, buf0, tid));
    store15(ra, pa); store15(rb, pb);
    __syncthreads();
    // invariant at loop top: chunk (s,[0,20)) in flight -> buf0; diag(s) in bufD

    for (int s = 0; s < NT - 1; ++s) {
        if (tid < 2) visit_diag(sm, (const float2*)bufD, s, tid);
        tileAB(s, m, A, B);
        pa = sm + 60 * A + 2 * cc;
        pb = sm + 60 * B + 2 * cc;
        PIPE(0, 20,   { stage(s, 20, 40, buf1, tid); stage_diag(s + 1, bufD, tid);
                        load15(ra, pa); load15(rb, pb); });
        PIPE(20, 40,   stage(s, 40, 60,  buf0, tid));
        PIPE(40, 60,   stage(s, 60, 80,  buf1, tid));
        PIPE(60, 80,   stage(s, 80, 100, buf0, tid));
        PIPE(80, 100,  stage(s, 100, 120, buf1, tid));
        PIPE(100, 120, stage(s, 120, 140, buf0, tid));
        PIPE(120, 140, stage(s, 140, 160, buf1, tid));
        PIPE(140, 160, stage(s, 160, 180, buf0, tid));
        PIPE(160, 180, stage(s, 180, 200, buf1, tid));
        PIPE(180, 200, stage(s, 200, 220, buf0, tid));
        PIPE(200, 220, stage(s, 220, 225, buf1, tid));
        PIPE(220, 225, stage(s + 1, 0, 20, buf0, tid));
        store15(ra, pa); store15(rb, pb);
        __syncthreads();
    }

    // ---- Epilogue: s = 272, early half (cells 0..119) ----
    {
        const int s = NT - 1;
        if (tid < 2) visit_diag(sm, (const float2*)bufD, s, tid);
        tileAB(s, m, A, B);
        pa = sm + 60 * A + 2 * cc;
        pb = sm + 60 * B + 2 * cc;
        PIPE(0, 20,   { stage(s, 20, 40, buf1, tid);
                        load15(ra, pa); load15(rb, pb); });
        PIPE(20, 40,   stage(s, 40, 60,  buf0, tid));
        PIPE(40, 60,   stage(s, 60, 80,  buf1, tid));
        PIPE(60, 80,   stage(s, 80, 100, buf0, tid));
        PIPE(80, 100,  stage(s, 100, 120, buf1, tid));
        PIPE(100, 120, { });
        store15(ra, pa); store15(rb, pb);
        __syncthreads();
    }

    // Writeback: slab u-row v -> absolute row x = 2v mod 4095 (4095 -> 4095)
    for (int v = tid; v < 4096; v += THREADS) {
        int x = (v == MM) ? MM : ((2 * v) % MM);
        float4 val = *(const float4*)(sm + v * CPT);
        *(float4*)(out + (size_t)x * 4096 + c0) = val;
    }
}

extern "C" void kernel_launch(void* const* d_in, const int* in_sizes, int n_in,
                              void* d_out, int out_size) {
    const float* thetas      = (const float*)d_in[0];
    const int*   round_theta = (const int*)d_in[3];
    float*       out         = (float*)d_out;
    (void)in_sizes; (void)n_in; (void)out_size;

    const int smem = SMEM_F * (int)sizeof(float);       // 112,768 B
    cudaFuncSetAttribute(rotmat_kernel,
                         cudaFuncAttributeMaxDynamicSharedMemorySize, smem);

    precompute<<<(int)((NPAIRS + 255) / 256), 256>>>(thetas, round_theta);

    rotmat_kernel<<<4096 / CPT, THREADS, smem>>>(out);
}